// round 1
// baseline (speedup 1.0000x reference)
#include <cuda_runtime.h>
#include <cuda_bf16.h>
#include <cstdint>

// Problem constants
#define BB 64
#define SS 512
#define EE 768
#define HH 256
#define G4 1024   // 4*H

// ---------------- scratch (device globals; no allocation allowed) ----------------
__device__ float g_xzf[BB * SS * G4];   // 134 MB  x @ kernel_f + bias_f
__device__ float g_xzb[BB * SS * G4];   // 134 MB  x @ kernel_b + bias_b
__device__ float g_hf[BB * SS * HH];    // 33.5 MB forward h history
__device__ float g_hb[BB * SS * HH];    // 33.5 MB backward h history (already un-reversed)
__device__ float g_hbuf[2][2][BB * HH]; // ping-pong h exchange buffers per direction
__device__ unsigned g_bar[2];           // per-direction barrier counters

// ---------------- init: zero barrier + h ping-pong buffers ----------------
__global__ void init_k() {
    int i = blockIdx.x * blockDim.x + threadIdx.x;
    if (i < 2) g_bar[i] = 0u;
    float* p = &g_hbuf[0][0][0];
    for (int k = i; k < 2 * 2 * BB * HH; k += gridDim.x * blockDim.x) p[k] = 0.f;
}

// ---------------- phase 1: xz = x @ W + bias, both directions ----------------
// GEMM M=32768 (B*S), K=768, N=1024. BM=128 BN=64 BK=16, 256 thr, 8x4 per thread.
__global__ __launch_bounds__(256) void gemm_xz(
    const float* __restrict__ x,
    const float* __restrict__ kf, const float* __restrict__ kb,
    const float* __restrict__ bf, const float* __restrict__ bb)
{
    __shared__ float As[16][132];   // [k][m], padded
    __shared__ float Bs[16][68];    // [k][n], padded

    const int dir = blockIdx.z;
    const float* W    = dir ? kb : kf;
    const float* bias = dir ? bb : bf;
    float* out        = dir ? g_xzb : g_xzf;

    const int t  = threadIdx.x;
    const int m0 = blockIdx.y * 128;
    const int n0 = blockIdx.x * 64;
    const int tx = t & 15, ty = t >> 4;

    float acc[8][4];
#pragma unroll
    for (int i = 0; i < 8; i++)
#pragma unroll
        for (int j = 0; j < 4; j++) acc[i][j] = 0.f;

    const int arow = t >> 2, akk = (t & 3) * 4;
    const int bkk = t >> 4, bnn = (t & 15) * 4;

    for (int k0 = 0; k0 < EE; k0 += 16) {
        float4 va0 = *(const float4*)(x + (size_t)(m0 + arow) * EE + k0 + akk);
        float4 va1 = *(const float4*)(x + (size_t)(m0 + arow + 64) * EE + k0 + akk);
        float4 vb  = *(const float4*)(W + (size_t)(k0 + bkk) * G4 + n0 + bnn);
        As[akk + 0][arow] = va0.x; As[akk + 1][arow] = va0.y;
        As[akk + 2][arow] = va0.z; As[akk + 3][arow] = va0.w;
        As[akk + 0][arow + 64] = va1.x; As[akk + 1][arow + 64] = va1.y;
        As[akk + 2][arow + 64] = va1.z; As[akk + 3][arow + 64] = va1.w;
        *(float4*)&Bs[bkk][bnn] = vb;
        __syncthreads();
#pragma unroll
        for (int k = 0; k < 16; k++) {
            float4 b4 = *(const float4*)&Bs[k][tx * 4];
            float4 a0 = *(const float4*)&As[k][ty * 8];
            float4 a1 = *(const float4*)&As[k][ty * 8 + 4];
            float av[8] = {a0.x, a0.y, a0.z, a0.w, a1.x, a1.y, a1.z, a1.w};
            float bv[4] = {b4.x, b4.y, b4.z, b4.w};
#pragma unroll
            for (int i = 0; i < 8; i++)
#pragma unroll
                for (int j = 0; j < 4; j++)
                    acc[i][j] = fmaf(av[i], bv[j], acc[i][j]);
        }
        __syncthreads();
    }

    float4 bv4 = *(const float4*)(bias + n0 + tx * 4);
#pragma unroll
    for (int i = 0; i < 8; i++) {
        int m = m0 + ty * 8 + i;
        float4 o;
        o.x = acc[i][0] + bv4.x; o.y = acc[i][1] + bv4.y;
        o.z = acc[i][2] + bv4.z; o.w = acc[i][3] + bv4.w;
        *(float4*)(out + (size_t)m * G4 + n0 + tx * 4) = o;
    }
}

// ---------------- phase 2: persistent bidirectional LSTM recurrence ----------------
// Grid = 128 CTAs: dir = bid>>6, g = bid&63. CTA owns h-cols [4g, 4g+4) => 16 gate cols.
// SMEM: hS (full h_prev, 64x256, padded 276/row, ks-blocked 68),
//       recS (16 gate cols x 256, lc stride 272, ks-blocked 68),
//       zp (k-split partials [4*64][17]).
// Thread roles: compute (bg = t>>4 [4 batches], j4 = (t>>2)&3, ks = t&3 [k-quarter]);
//               final   (fb = t>>2 [batch], fj = t&3 [local h col]) -> owns c-state reg.
#define HS_B 276
#define HS_K 68
#define RC_L 272
#define RC_K 68
#define SMEM_FLOATS (BB * HS_B + 16 * RC_L + 256 * 17)

__global__ __launch_bounds__(256) void lstm_rec(
    const float* __restrict__ rec_f, const float* __restrict__ rec_b)
{
    extern __shared__ float sm[];
    float* hS   = sm;
    float* recS = sm + BB * HS_B;
    float* zp   = sm + BB * HS_B + 16 * RC_L;

    const int t   = threadIdx.x;
    const int dir = blockIdx.x >> 6;
    const int g   = blockIdx.x & 63;
    const int hc0 = g * 4;

    const float* rec  = dir ? rec_b : rec_f;
    const float* xz   = dir ? g_xzb : g_xzf;
    float*       hist = dir ? g_hb  : g_hf;

    // load rec slice: recS[lc][ks][k&63], lc = q*4+j, global col = q*256 + hc0 + j
    for (int idx = t; idx < 16 * HH; idx += 256) {
        int lc = idx >> 8, k = idx & 255;
        int col = (lc >> 2) * HH + hc0 + (lc & 3);
        recS[lc * RC_L + (k >> 6) * RC_K + (k & 63)] = rec[k * G4 + col];
    }

    const int bg = t >> 4, j4 = (t >> 2) & 3, ks = t & 3;
    const int fb = t >> 2, fj = t & 3;
    float c_state = 0.f;

    const float* hP0 = &hS[(bg * 4 + 0) * HS_B + ks * HS_K];
    const float* hP1 = &hS[(bg * 4 + 1) * HS_B + ks * HS_K];
    const float* hP2 = &hS[(bg * 4 + 2) * HS_B + ks * HS_K];
    const float* hP3 = &hS[(bg * 4 + 3) * HS_B + ks * HS_K];
    const float* rP0 = &recS[(0 * 4 + j4) * RC_L + ks * RC_K];
    const float* rP1 = &recS[(1 * 4 + j4) * RC_L + ks * RC_K];
    const float* rP2 = &recS[(2 * 4 + j4) * RC_L + ks * RC_K];
    const float* rP3 = &recS[(3 * 4 + j4) * RC_L + ks * RC_K];

    __syncthreads();

    for (int step = 0; step < SS; step++) {
        const float* hcur  = &g_hbuf[dir][step & 1][0];
        float*       hnext = &g_hbuf[dir][(step + 1) & 1][0];

        // fill hS from global ping buffer (L1-bypassed: other SMs wrote it)
#pragma unroll
        for (int i = 0; i < 16; i++) {
            int lin4 = t + 256 * i;               // float4 index into 16384 floats
            float4 v = __ldcg((const float4*)(hcur + lin4 * 4));
            int b = lin4 >> 6, k4 = lin4 & 63;    // k4: float4 col 0..63
            *(float4*)&hS[b * HS_B + (k4 >> 4) * HS_K + (k4 & 15) * 4] = v;
        }
        __syncthreads();

        // compute partial dot products: acc[gate q][batch bb] over k quarter ks
        float acc[4][4];
#pragma unroll
        for (int q = 0; q < 4; q++)
#pragma unroll
            for (int b2 = 0; b2 < 4; b2++) acc[q][b2] = 0.f;

#pragma unroll 8
        for (int c = 0; c < 16; c++) {
            float4 r0 = *(const float4*)(rP0 + c * 4);
            float4 r1 = *(const float4*)(rP1 + c * 4);
            float4 r2 = *(const float4*)(rP2 + c * 4);
            float4 r3 = *(const float4*)(rP3 + c * 4);
            float4 h0 = *(const float4*)(hP0 + c * 4);
            float4 h1 = *(const float4*)(hP1 + c * 4);
            float4 h2 = *(const float4*)(hP2 + c * 4);
            float4 h3 = *(const float4*)(hP3 + c * 4);
#define DOT4(q, r, b2, h)  acc[q][b2] = fmaf(r.x, h.x, fmaf(r.y, h.y, fmaf(r.z, h.z, fmaf(r.w, h.w, acc[q][b2]))))
            DOT4(0, r0, 0, h0); DOT4(0, r0, 1, h1); DOT4(0, r0, 2, h2); DOT4(0, r0, 3, h3);
            DOT4(1, r1, 0, h0); DOT4(1, r1, 1, h1); DOT4(1, r1, 2, h2); DOT4(1, r1, 3, h3);
            DOT4(2, r2, 0, h0); DOT4(2, r2, 1, h1); DOT4(2, r2, 2, h2); DOT4(2, r2, 3, h3);
            DOT4(3, r3, 0, h0); DOT4(3, r3, 1, h1); DOT4(3, r3, 2, h2); DOT4(3, r3, 3, h3);
#undef DOT4
        }

#pragma unroll
        for (int q = 0; q < 4; q++)
#pragma unroll
            for (int b2 = 0; b2 < 4; b2++)
                zp[(ks * 64 + (bg * 4 + b2)) * 17 + q * 4 + j4] = acc[q][b2];
        __syncthreads();

        // final: reduce partials, gate math, state update, publish h
        {
            int spos = dir ? (SS - 1 - step) : step;
            const float* xzr = xz + ((size_t)fb * SS + spos) * G4 + hc0 + fj;
            float z[4];
#pragma unroll
            for (int q = 0; q < 4; q++) {
                float s = __ldg(xzr + q * HH);
#pragma unroll
                for (int kk = 0; kk < 4; kk++)
                    s += zp[(kk * 64 + fb) * 17 + q * 4 + fj];
                z[q] = s;
            }
            float ig = 1.f / (1.f + __expf(-z[0]));
            float fg = 1.f / (1.f + __expf(-z[1]));
            float og = 1.f / (1.f + __expf(-z[3]));
            float cc = fmaxf(z[2], 0.f);
            c_state = fg * c_state + ig * cc;
            float h = og * fmaxf(c_state, 0.f);
            __stcg(hnext + fb * HH + hc0 + fj, h);
            hist[(size_t)fb * (SS * HH) + (size_t)spos * HH + hc0 + fj] = h;
        }

        // inter-CTA barrier (per direction, 64 CTAs)
        __threadfence();
        __syncthreads();
        if (t == 0) {
            atomicAdd(&g_bar[dir], 1u);
            unsigned tgt = 64u * (unsigned)(step + 1);
            while (*((volatile unsigned*)&g_bar[dir]) < tgt) __nanosleep(40);
        }
        __syncthreads();
        __threadfence();
    }
}

// ---------------- phase 3: logits = (hf + hb).reshape(B,-1) @ Wd + bd ----------------
__global__ __launch_bounds__(256) void dense_out(
    const float* __restrict__ Wd, const float* __restrict__ bd, float* __restrict__ out)
{
    __shared__ float s0[256], s1[256];
    const int b = blockIdx.x, t = threadIdx.x;
    const float* hf = g_hf + (size_t)b * (SS * HH);
    const float* hb = g_hb + (size_t)b * (SS * HH);
    float a0 = 0.f, a1 = 0.f;
    for (int i = t * 4; i < SS * HH; i += 256 * 4) {
        float4 vf = *(const float4*)(hf + i);
        float4 vb = *(const float4*)(hb + i);
        float4 w0 = *(const float4*)(Wd + 2 * i);
        float4 w1 = *(const float4*)(Wd + 2 * i + 4);
        float v0 = vf.x + vb.x, v1 = vf.y + vb.y, v2 = vf.z + vb.z, v3 = vf.w + vb.w;
        a0 = fmaf(v0, w0.x, a0); a1 = fmaf(v0, w0.y, a1);
        a0 = fmaf(v1, w0.z, a0); a1 = fmaf(v1, w0.w, a1);
        a0 = fmaf(v2, w1.x, a0); a1 = fmaf(v2, w1.y, a1);
        a0 = fmaf(v3, w1.z, a0); a1 = fmaf(v3, w1.w, a1);
    }
    s0[t] = a0; s1[t] = a1;
    __syncthreads();
    for (int s = 128; s > 0; s >>= 1) {
        if (t < s) { s0[t] += s0[t + s]; s1[t] += s1[t + s]; }
        __syncthreads();
    }
    if (t == 0) {
        out[b * 2 + 0] = s0[0] + bd[0];
        out[b * 2 + 1] = s1[0] + bd[1];
    }
}

// ---------------- launcher ----------------
extern "C" void kernel_launch(void* const* d_in, const int* in_sizes, int n_in,
                              void* d_out, int out_size)
{
    const float* x  = (const float*)d_in[0];
    const float* kf = (const float*)d_in[1];
    const float* rf = (const float*)d_in[2];
    const float* bf = (const float*)d_in[3];
    const float* kb = (const float*)d_in[4];
    const float* rb = (const float*)d_in[5];
    const float* bbv= (const float*)d_in[6];
    const float* Wd = (const float*)d_in[7];
    const float* bd = (const float*)d_in[8];
    float* out = (float*)d_out;

    init_k<<<64, 256>>>();
    gemm_xz<<<dim3(G4 / 64, (BB * SS) / 128, 2), 256>>>(x, kf, kb, bf, bbv);

    const int smem_bytes = SMEM_FLOATS * (int)sizeof(float);
    cudaFuncSetAttribute(lstm_rec, cudaFuncAttributeMaxDynamicSharedMemorySize, smem_bytes);
    lstm_rec<<<128, 256, smem_bytes>>>(rf, rb);

    dense_out<<<BB, 256>>>(Wd, bd, out);
}

// round 3
// speedup vs baseline: 1.3109x; 1.3109x over previous
#include <cuda_runtime.h>
#include <cuda_bf16.h>
#include <cstdint>

// Problem constants
#define BB 64
#define SS 512
#define EE 768
#define HH 256
#define G4 1024    // 4*H
#define MM (BB*SS) // 32768 rows

// ---------------- scratch (device globals; no allocation allowed) ----------------
__device__ float g_xzf[MM * G4];        // x @ kernel_f + bias_f
__device__ float g_xzb[MM * G4];        // x @ kernel_b + bias_b
__device__ float g_hf[MM * HH];         // forward h history
__device__ float g_hb[MM * HH];         // backward h history (un-reversed)
__device__ float g_hbuf[2][2][BB * HH]; // ping-pong h exchange buffers per direction
__device__ unsigned g_bar[2];           // per-direction barrier counters

// bf16 split operands for tensor-core GEMM
__device__ __nv_bfloat16 g_xh[MM * EE];           // hi(x)
__device__ __nv_bfloat16 g_xl[MM * EE];           // lo(x)
__device__ __nv_bfloat16 g_wt[2][2][G4 * EE];     // [dir][hi/lo] W^T as [n][k]

// ---------------- PTX helpers ----------------
__device__ __forceinline__ uint32_t smem_u32(const void* p) {
    uint32_t a;
    asm("{ .reg .u64 t; cvta.to.shared.u64 t, %1; cvt.u32.u64 %0, t; }" : "=r"(a) : "l"(p));
    return a;
}
__device__ __forceinline__ void cp16(uint32_t s, const void* g) {
    asm volatile("cp.async.cg.shared.global [%0], [%1], 16;" :: "r"(s), "l"(g));
}
#define CP_COMMIT() asm volatile("cp.async.commit_group;" ::: "memory")
#define CP_WAIT0()  asm volatile("cp.async.wait_group 0;" ::: "memory")

#define LDSM4(R, addr) \
    asm volatile("ldmatrix.sync.aligned.m8n8.x4.shared.b16 {%0,%1,%2,%3}, [%4];" \
        : "=r"((R)[0]), "=r"((R)[1]), "=r"((R)[2]), "=r"((R)[3]) : "r"(addr))

#define MMA16816(d, a, b) \
    asm volatile("mma.sync.aligned.m16n8k16.row.col.f32.bf16.bf16.f32 " \
        "{%0,%1,%2,%3}, {%4,%5,%6,%7}, {%8,%9}, {%0,%1,%2,%3};" \
        : "+f"((d)[0]), "+f"((d)[1]), "+f"((d)[2]), "+f"((d)[3]) \
        : "r"((a)[0]), "r"((a)[1]), "r"((a)[2]), "r"((a)[3]), "r"((b)[0]), "r"((b)[1]))

// ---------------- init: zero barrier + h ping-pong buffers ----------------
__global__ void init_k() {
    int i = blockIdx.x * blockDim.x + threadIdx.x;
    if (i < 2) g_bar[i] = 0u;
    float* p = &g_hbuf[0][0][0];
    for (int k = i; k < 2 * 2 * BB * HH; k += gridDim.x * blockDim.x) p[k] = 0.f;
}

// ---------------- prep: bf16 hi/lo split of x, and W^T splits ----------------
__global__ __launch_bounds__(256) void split_x(const float* __restrict__ x) {
    int stride = gridDim.x * blockDim.x;
    for (int i = blockIdx.x * blockDim.x + threadIdx.x; i < MM * EE; i += stride) {
        float v = x[i];
        __nv_bfloat16 h = __float2bfloat16(v);
        g_xh[i] = h;
        g_xl[i] = __float2bfloat16(v - __bfloat162float(h));
    }
}
__global__ __launch_bounds__(256) void split_w(const float* __restrict__ kf,
                                               const float* __restrict__ kb) {
    int stride = gridDim.x * blockDim.x;
    for (int i = blockIdx.x * blockDim.x + threadIdx.x; i < EE * G4; i += stride) {
        int n = i & (G4 - 1), k = i >> 10;
        float vf = kf[i], vb = kb[i];
        __nv_bfloat16 hf16 = __float2bfloat16(vf);
        __nv_bfloat16 hb16 = __float2bfloat16(vb);
        g_wt[0][0][n * EE + k] = hf16;
        g_wt[0][1][n * EE + k] = __float2bfloat16(vf - __bfloat162float(hf16));
        g_wt[1][0][n * EE + k] = hb16;
        g_wt[1][1][n * EE + k] = __float2bfloat16(vb - __bfloat162float(hb16));
    }
}

// ---------------- phase 1: mma.sync bf16 GEMM  xz = x @ W + bias ----------------
// 3-term split as uniform GEMM over K' = 3*768: chunks [0,24)=Ah*Bh,
// [24,48)=Al*Bh, [48,72)=Ah*Bl. CTA tile 128x128, BK=32, 2-stage cp.async.
// 8 warps as 4(M) x 2(N): warp tile 32x64. m16n8k16 bf16 HMMA.
#define NKCH 72

__global__ __launch_bounds__(256) void gemm_mma(
    const float* __restrict__ bias_f, const float* __restrict__ bias_b)
{
    __shared__ __align__(16) __nv_bfloat16 sA[2][128][40];
    __shared__ __align__(16) __nv_bfloat16 sB[2][128][40];

    const int t = threadIdx.x, lane = t & 31, w = t >> 5;
    const int dir = blockIdx.z;
    const int m0 = blockIdx.y * 128;
    const int n0 = blockIdx.x * 128;

    const __nv_bfloat16* wth = &g_wt[dir][0][0];
    const __nv_bfloat16* wtl = &g_wt[dir][1][0];
    const float* bias = dir ? bias_b : bias_f;
    float* out = dir ? g_xzb : g_xzf;

    const uint32_t sAu = smem_u32(&sA[0][0][0]);
    const uint32_t sBu = smem_u32(&sB[0][0][0]);

    float acc[2][8][4];
#pragma unroll
    for (int i = 0; i < 2; i++)
#pragma unroll
        for (int j = 0; j < 8; j++)
#pragma unroll
            for (int k = 0; k < 4; k++) acc[i][j][k] = 0.f;

    // loader indices: 512 16B-segments each for A and B; 2 per thread each
    const int lr0 = t >> 2, lc0 = t & 3;          // seg t
    const int lr1 = (t + 256) >> 2;               // seg t+256 (same lc0)

    // ldmatrix fragment addresses
    const int wm = (w & 3) * 32, wn = (w >> 2) * 64;
    const int aRow = wm + (lane & 15);
    const int aCol = (lane >> 4) * 8;
    const int bRow = wn + (lane & 7) + ((lane & 16) ? 8 : 0);
    const int bCol = ((lane >> 3) & 1) * 8;

#define LOAD_CHUNK(kc, buf) do {                                                  \
    int p_ = (kc) / 24, kk_ = (kc) - p_ * 24;                                     \
    const __nv_bfloat16* Ag_ = (p_ == 1) ? g_xl : g_xh;                           \
    const __nv_bfloat16* Bg_ = (p_ == 2) ? wtl : wth;                             \
    cp16(sAu + (((buf) * 128 + lr0) * 40 + lc0 * 8) * 2,                          \
         Ag_ + (size_t)(m0 + lr0) * EE + kk_ * 32 + lc0 * 8);                     \
    cp16(sAu + (((buf) * 128 + lr1) * 40 + lc0 * 8) * 2,                          \
         Ag_ + (size_t)(m0 + lr1) * EE + kk_ * 32 + lc0 * 8);                     \
    cp16(sBu + (((buf) * 128 + lr0) * 40 + lc0 * 8) * 2,                          \
         Bg_ + (size_t)(n0 + lr0) * EE + kk_ * 32 + lc0 * 8);                     \
    cp16(sBu + (((buf) * 128 + lr1) * 40 + lc0 * 8) * 2,                          \
         Bg_ + (size_t)(n0 + lr1) * EE + kk_ * 32 + lc0 * 8);                     \
} while (0)

    LOAD_CHUNK(0, 0);
    CP_COMMIT();

    for (int kc = 0; kc < NKCH; kc++) {
        const int buf = kc & 1;
        CP_WAIT0();
        __syncthreads();
        if (kc + 1 < NKCH) { LOAD_CHUNK(kc + 1, buf ^ 1); CP_COMMIT(); }

#pragma unroll
        for (int k16 = 0; k16 < 32; k16 += 16) {
            uint32_t a[2][4];
#pragma unroll
            for (int mt = 0; mt < 2; mt++)
                LDSM4(a[mt], sAu + ((buf * 128 + aRow + mt * 16) * 40 + k16 + aCol) * 2);
            uint32_t b[8][2];
#pragma unroll
            for (int i = 0; i < 4; i++) {
                uint32_t r[4];
                LDSM4(r, sBu + ((buf * 128 + bRow + i * 16) * 40 + k16 + bCol) * 2);
                b[2 * i][0] = r[0]; b[2 * i][1] = r[1];
                b[2 * i + 1][0] = r[2]; b[2 * i + 1][1] = r[3];
            }
#pragma unroll
            for (int mt = 0; mt < 2; mt++)
#pragma unroll
                for (int nt = 0; nt < 8; nt++)
                    MMA16816(acc[mt][nt], a[mt], b[nt]);
        }
        __syncthreads();
    }
#undef LOAD_CHUNK

    // epilogue: direct register stores (+bias). 32B-sector aligned float2 stores.
#pragma unroll
    for (int nt = 0; nt < 8; nt++) {
        const int col = n0 + wn + nt * 8 + (lane & 3) * 2;
        const float b0 = __ldg(bias + col), b1 = __ldg(bias + col + 1);
#pragma unroll
        for (int mt = 0; mt < 2; mt++) {
            const int r0 = m0 + wm + mt * 16 + (lane >> 2);
            float2 v0 = make_float2(acc[mt][nt][0] + b0, acc[mt][nt][1] + b1);
            float2 v1 = make_float2(acc[mt][nt][2] + b0, acc[mt][nt][3] + b1);
            *(float2*)(out + (size_t)r0 * G4 + col) = v0;
            *(float2*)(out + (size_t)(r0 + 8) * G4 + col) = v1;
        }
    }
}

// ---------------- phase 2: persistent bidirectional LSTM recurrence ----------------
#define HS_B 276
#define HS_K 68
#define RC_L 272
#define RC_K 68
#define SMEM_FLOATS (BB * HS_B + 16 * RC_L + 256 * 17)

__global__ __launch_bounds__(256) void lstm_rec(
    const float* __restrict__ rec_f, const float* __restrict__ rec_b)
{
    extern __shared__ float sm[];
    float* hS   = sm;
    float* recS = sm + BB * HS_B;
    float* zp   = sm + BB * HS_B + 16 * RC_L;

    const int t   = threadIdx.x;
    const int dir = blockIdx.x >> 6;
    const int g   = blockIdx.x & 63;
    const int hc0 = g * 4;

    const float* rec  = dir ? rec_b : rec_f;
    const float* xz   = dir ? g_xzb : g_xzf;
    float*       hist = dir ? g_hb  : g_hf;

    for (int idx = t; idx < 16 * HH; idx += 256) {
        int lc = idx >> 8, k = idx & 255;
        int col = (lc >> 2) * HH + hc0 + (lc & 3);
        recS[lc * RC_L + (k >> 6) * RC_K + (k & 63)] = rec[k * G4 + col];
    }

    const int bg = t >> 4, j4 = (t >> 2) & 3, ks = t & 3;
    const int fb = t >> 2, fj = t & 3;
    float c_state = 0.f;

    const float* hP0 = &hS[(bg * 4 + 0) * HS_B + ks * HS_K];
    const float* hP1 = &hS[(bg * 4 + 1) * HS_B + ks * HS_K];
    const float* hP2 = &hS[(bg * 4 + 2) * HS_B + ks * HS_K];
    const float* hP3 = &hS[(bg * 4 + 3) * HS_B + ks * HS_K];
    const float* rP0 = &recS[(0 * 4 + j4) * RC_L + ks * RC_K];
    const float* rP1 = &recS[(1 * 4 + j4) * RC_L + ks * RC_K];
    const float* rP2 = &recS[(2 * 4 + j4) * RC_L + ks * RC_K];
    const float* rP3 = &recS[(3 * 4 + j4) * RC_L + ks * RC_K];

    __syncthreads();

    for (int step = 0; step < SS; step++) {
        const float* hcur  = &g_hbuf[dir][step & 1][0];
        float*       hnext = &g_hbuf[dir][(step + 1) & 1][0];

#pragma unroll
        for (int i = 0; i < 16; i++) {
            int lin4 = t + 256 * i;
            float4 v = __ldcg((const float4*)(hcur + lin4 * 4));
            int b = lin4 >> 6, k4 = lin4 & 63;
            *(float4*)&hS[b * HS_B + (k4 >> 4) * HS_K + (k4 & 15) * 4] = v;
        }
        __syncthreads();

        float acc[4][4];
#pragma unroll
        for (int q = 0; q < 4; q++)
#pragma unroll
            for (int b2 = 0; b2 < 4; b2++) acc[q][b2] = 0.f;

#pragma unroll 8
        for (int c = 0; c < 16; c++) {
            float4 r0 = *(const float4*)(rP0 + c * 4);
            float4 r1 = *(const float4*)(rP1 + c * 4);
            float4 r2 = *(const float4*)(rP2 + c * 4);
            float4 r3 = *(const float4*)(rP3 + c * 4);
            float4 h0 = *(const float4*)(hP0 + c * 4);
            float4 h1 = *(const float4*)(hP1 + c * 4);
            float4 h2 = *(const float4*)(hP2 + c * 4);
            float4 h3 = *(const float4*)(hP3 + c * 4);
#define DOT4(q, r, b2, h)  acc[q][b2] = fmaf(r.x, h.x, fmaf(r.y, h.y, fmaf(r.z, h.z, fmaf(r.w, h.w, acc[q][b2]))))
            DOT4(0, r0, 0, h0); DOT4(0, r0, 1, h1); DOT4(0, r0, 2, h2); DOT4(0, r0, 3, h3);
            DOT4(1, r1, 0, h0); DOT4(1, r1, 1, h1); DOT4(1, r1, 2, h2); DOT4(1, r1, 3, h3);
            DOT4(2, r2, 0, h0); DOT4(2, r2, 1, h1); DOT4(2, r2, 2, h2); DOT4(2, r2, 3, h3);
            DOT4(3, r3, 0, h0); DOT4(3, r3, 1, h1); DOT4(3, r3, 2, h2); DOT4(3, r3, 3, h3);
#undef DOT4
        }

#pragma unroll
        for (int q = 0; q < 4; q++)
#pragma unroll
            for (int b2 = 0; b2 < 4; b2++)
                zp[(ks * 64 + (bg * 4 + b2)) * 17 + q * 4 + j4] = acc[q][b2];
        __syncthreads();

        {
            int spos = dir ? (SS - 1 - step) : step;
            const float* xzr = xz + ((size_t)fb * SS + spos) * G4 + hc0 + fj;
            float z[4];
#pragma unroll
            for (int q = 0; q < 4; q++) {
                float s = __ldg(xzr + q * HH);
#pragma unroll
                for (int kk = 0; kk < 4; kk++)
                    s += zp[(kk * 64 + fb) * 17 + q * 4 + fj];
                z[q] = s;
            }
            float ig = 1.f / (1.f + __expf(-z[0]));
            float fg = 1.f / (1.f + __expf(-z[1]));
            float og = 1.f / (1.f + __expf(-z[3]));
            float cc = fmaxf(z[2], 0.f);
            c_state = fg * c_state + ig * cc;
            float h = og * fmaxf(c_state, 0.f);
            __stcg(hnext + fb * HH + hc0 + fj, h);
            hist[(size_t)fb * (SS * HH) + (size_t)spos * HH + hc0 + fj] = h;
        }

        __threadfence();
        __syncthreads();
        if (t == 0) {
            atomicAdd(&g_bar[dir], 1u);
            unsigned tgt = 64u * (unsigned)(step + 1);
            while (*((volatile unsigned*)&g_bar[dir]) < tgt) __nanosleep(40);
        }
        __syncthreads();
        __threadfence();
    }
}

// ---------------- phase 3: logits = (hf + hb).reshape(B,-1) @ Wd + bd ----------------
__global__ __launch_bounds__(256) void dense_out(
    const float* __restrict__ Wd, const float* __restrict__ bd, float* __restrict__ out)
{
    __shared__ float s0[256], s1[256];
    const int b = blockIdx.x, t = threadIdx.x;
    const float* hf = g_hf + (size_t)b * (SS * HH);
    const float* hb = g_hb + (size_t)b * (SS * HH);
    float a0 = 0.f, a1 = 0.f;
    for (int i = t * 4; i < SS * HH; i += 256 * 4) {
        float4 vf = *(const float4*)(hf + i);
        float4 vb = *(const float4*)(hb + i);
        float4 w0 = *(const float4*)(Wd + 2 * i);
        float4 w1 = *(const float4*)(Wd + 2 * i + 4);
        float v0 = vf.x + vb.x, v1 = vf.y + vb.y, v2 = vf.z + vb.z, v3 = vf.w + vb.w;
        a0 = fmaf(v0, w0.x, a0); a1 = fmaf(v0, w0.y, a1);
        a0 = fmaf(v1, w0.z, a0); a1 = fmaf(v1, w0.w, a1);
        a0 = fmaf(v2, w1.x, a0); a1 = fmaf(v2, w1.y, a1);
        a0 = fmaf(v3, w1.z, a0); a1 = fmaf(v3, w1.w, a1);
    }
    s0[t] = a0; s1[t] = a1;
    __syncthreads();
    for (int s = 128; s > 0; s >>= 1) {
        if (t < s) { s0[t] += s0[t + s]; s1[t] += s1[t + s]; }
        __syncthreads();
    }
    if (t == 0) {
        out[b * 2 + 0] = s0[0] + bd[0];
        out[b * 2 + 1] = s1[0] + bd[1];
    }
}

// ---------------- launcher ----------------
extern "C" void kernel_launch(void* const* d_in, const int* in_sizes, int n_in,
                              void* d_out, int out_size)
{
    const float* x  = (const float*)d_in[0];
    const float* kf = (const float*)d_in[1];
    const float* rf = (const float*)d_in[2];
    const float* bf = (const float*)d_in[3];
    const float* kb = (const float*)d_in[4];
    const float* rb = (const float*)d_in[5];
    const float* bbv= (const float*)d_in[6];
    const float* Wd = (const float*)d_in[7];
    const float* bd = (const float*)d_in[8];
    float* out = (float*)d_out;

    init_k<<<64, 256>>>();
    split_x<<<4096, 256>>>(x);
    split_w<<<1024, 256>>>(kf, kb);

    gemm_mma<<<dim3(G4 / 128, MM / 128, 2), 256>>>(bf, bbv);

    const int smem_bytes = SMEM_FLOATS * (int)sizeof(float);
    cudaFuncSetAttribute(lstm_rec, cudaFuncAttributeMaxDynamicSharedMemorySize, smem_bytes);
    lstm_rec<<<128, 256, smem_bytes>>>(rf, rb);

    dense_out<<<BB, 256>>>(Wd, bd, out);
}